// round 6
// baseline (speedup 1.0000x reference)
#include <cuda_runtime.h>
#include <cuda_fp16.h>
#include <cstdint>

// Problem constants (fixed by the dataset)
#define NC   1000      // cells
#define NGOI 500       // genes of interest
#define NGT  5000      // total genes
#define NL   10        // latent dim
#define NK   129       // knots (NBINS+1)
#define NPAIR (NC*NGOI)
#define NKEY  NPAIR            // sort key space: j*NC + cell
#define MAXCUTS 1000000
#define SCHUNK 1024
#define SNBLK ((NKEY + SCHUNK - 1) / SCHUNK)   // 489

#define CSPLIT 8
#define CPB (NC / CSPLIT)      // 125 cells per block
#define FUSED_BLOCKS (NGOI * CSPLIT)           // 4000

// ---------------- device scratch (static: no allocation allowed) -------------
__device__ float  g_logits[NC * NGT];          // 20 MB raw logits
__device__ float  g_lse[NC];
__device__ __half g_B[NGOI * 128];             // 128 KB exp(baseline) knots 0..127
__device__ __half g_B128[NGOI];                // exp(baseline) knot 128
__device__ int    g_cnt[NKEY];                 // per-key cut counts
__device__ int    g_start[NKEY];               // exclusive prefix (CSR row ptr)
__device__ int    g_cursor[NKEY];              // scatter cursors
__device__ int    g_bsum[SNBLK];               // scan block sums
__device__ uint2  g_rec[MAXCUTS];              // sorted cut records {x, (q<<9)|gl}
__device__ double g_part[FUSED_BLOCKS];

// ---------------- kernel: overall logits [NC x NGT] --------------------------
__global__ void k_logits(const float* __restrict__ latent,
                         const float* __restrict__ wo,
                         const float* __restrict__ ob) {
    __shared__ float lat[16 * NL];
    int g  = blockIdx.x * 256 + threadIdx.x;
    int c0 = blockIdx.y * 16;
    int t = threadIdx.x;
    if (t < 16 * NL) {
        int cc = c0 + t / NL;
        lat[t] = (cc < NC) ? latent[cc * NL + t % NL] : 0.f;
    }
    __syncthreads();
    if (g >= NGT) return;
    float w[NL];
#pragma unroll
    for (int l = 0; l < NL; l++) w[l] = wo[g * NL + l];
    float base = ob[g];
    int cmax = NC - c0; if (cmax > 16) cmax = 16;
    for (int c = 0; c < cmax; c++) {
        float a = base;
#pragma unroll
        for (int l = 0; l < NL; l++) a = fmaf(lat[c * NL + l], w[l], a);
        g_logits[(c0 + c) * NGT + g] = a;
    }
}

// ---------------- kernel: per-cell log-sum-exp --------------------------------
__global__ void k_lse() {
    int c = blockIdx.x;
    const float4* row = (const float4*)&g_logits[c * NGT];
    float s = 0.f;
    for (int i = threadIdx.x; i < NGT / 4; i += 512) {
        float4 v = row[i];
        s += __expf(v.x) + __expf(v.y) + __expf(v.z) + __expf(v.w);
    }
    __shared__ float sh[16];
#pragma unroll
    for (int o = 16; o; o >>= 1) s += __shfl_xor_sync(0xffffffffu, s, o);
    if ((threadIdx.x & 31) == 0) sh[threadIdx.x >> 5] = s;
    __syncthreads();
    if (threadIdx.x < 16) {
        s = sh[threadIdx.x];
#pragma unroll
        for (int o = 8; o; o >>= 1) s += __shfl_xor_sync(0xffffu, s, o);
        if (threadIdx.x == 0) g_lse[c] = __logf(s);
    }
}

// ---------------- kernel: baseline exp table ----------------------------------
__global__ void k_bexp(const float* __restrict__ sb, const int* __restrict__ goi) {
    int j = blockIdx.x;
    int gene = goi[j];
    int t = threadIdx.x;
    if (t < NK) {
        __half v = __float2half_rn(__expf(sb[(size_t)gene * NK + t]));
        if (t < 128) g_B[j * 128 + t] = v;
        else         g_B128[j] = v;
    }
}

// ---------------- counting sort: zero / hist / scan / scatter -----------------
__global__ void k_zero() {
    int i = blockIdx.x * 256 + threadIdx.x;
    if (i < NKEY) g_cnt[i] = 0;
}

__global__ void k_hist(const int* __restrict__ cxg, int ncuts) {
    int i = blockIdx.x * 256 + threadIdx.x;
    if (i >= ncuts) return;
    unsigned p = (unsigned)cxg[i];
    unsigned key = (p % NGOI) * NC + p / NGOI;
    atomicAdd(&g_cnt[key], 1);
}

__global__ void k_scanA() {
    __shared__ int sh[2][256];
    int t = threadIdx.x;
    int base = blockIdx.x * SCHUNK + t * 4;
    int x0 = 0, x1 = 0, x2 = 0, x3 = 0;
    if (base + 0 < NKEY) x0 = g_cnt[base + 0];
    if (base + 1 < NKEY) x1 = g_cnt[base + 1];
    if (base + 2 < NKEY) x2 = g_cnt[base + 2];
    if (base + 3 < NKEY) x3 = g_cnt[base + 3];
    int ts = x0 + x1 + x2 + x3;
    int buf = 0;
    sh[0][t] = ts;
    __syncthreads();
#pragma unroll
    for (int off = 1; off < 256; off <<= 1) {
        int v = sh[buf][t] + ((t >= off) ? sh[buf][t - off] : 0);
        sh[buf ^ 1][t] = v;
        buf ^= 1;
        __syncthreads();
    }
    int incl = sh[buf][t];
    int excl = incl - ts;
    if (t == 255) g_bsum[blockIdx.x] = incl;
    int p0 = excl, p1 = p0 + x0, p2 = p1 + x1, p3 = p2 + x2;
    if (base + 0 < NKEY) g_start[base + 0] = p0;
    if (base + 1 < NKEY) g_start[base + 1] = p1;
    if (base + 2 < NKEY) g_start[base + 2] = p2;
    if (base + 3 < NKEY) g_start[base + 3] = p3;
}

__global__ void k_scanB() {
    __shared__ int sh[2][512];
    int t = threadIdx.x;
    int v = (t < SNBLK) ? g_bsum[t] : 0;
    int buf = 0;
    sh[0][t] = v;
    __syncthreads();
#pragma unroll
    for (int off = 1; off < 512; off <<= 1) {
        int nv = sh[buf][t] + ((t >= off) ? sh[buf][t - off] : 0);
        sh[buf ^ 1][t] = nv;
        buf ^= 1;
        __syncthreads();
    }
    if (t < SNBLK) g_bsum[t] = sh[buf][t] - v;   // exclusive
}

__global__ void k_scanC() {
    int i = blockIdx.x * 256 + threadIdx.x;
    if (i >= NKEY) return;
    int v = g_start[i] + g_bsum[i >> 10];
    g_start[i] = v;
    g_cursor[i] = v;
}

__global__ void k_scatter(const float* __restrict__ coord,
                          const int*   __restrict__ cxg,
                          const int*   __restrict__ lcxg,
                          const int*   __restrict__ gloc,
                          int ncuts) {
    int i = blockIdx.x * 256 + threadIdx.x;
    if (i >= ncuts) return;
    unsigned p = (unsigned)cxg[i];
    unsigned key = (p % NGOI) * NC + p / NGOI;
    int pos = atomicAdd(&g_cursor[key], 1);
    unsigned q  = (unsigned)lcxg[i];
    unsigned gl = (unsigned)gloc[i];
    g_rec[pos] = make_uint2(__float_as_uint(coord[i]), (q << 9) | gl);
}

// ---------------- fused kernel: delta-exp in regs + per-cut spline ------------
// block = (gene j, cell chunk); warp per cell; lane owns knots 4*lane..4*lane+3
__global__ void __launch_bounds__(256) k_fused(const float* __restrict__ latent,
                                               const float* __restrict__ hw,
                                               const int*   __restrict__ goi) {
    __shared__ float slat[CPB * 12];
    __shared__ float sE128[CPB];        // exp(delta at knot 128) per cell
    int j = blockIdx.x;
    int gene = goi[j];
    int c0 = blockIdx.y * CPB;
    int tid = threadIdx.x;
    int w = tid >> 5, lane = tid & 31;
    const float C = 4.852030263919617f + 8.517193191416238f; // ln(128)+ln(5000)
    const unsigned FULL = 0xffffffffu;

    for (int i = tid; i < CPB * NL; i += 256) {
        int cc = i / NL, l = i - cc * NL;
        slat[cc * 12 + l] = latent[(c0 + cc) * NL + l];
    }

    int k4 = lane * 4;
    const float* wp = hw + (size_t)gene * NL * NK;
    float W0[NL], W1[NL], W2[NL], W3[NL];
#pragma unroll
    for (int l = 0; l < NL; l++) {
        const float* r = wp + l * NK;
        W0[l] = r[k4];     W1[l] = r[k4 + 1];
        W2[l] = r[k4 + 2]; W3[l] = r[k4 + 3];
    }
    __syncthreads();

    // per-cell knot-128 delta (threads 0..124)
    if (tid < CPB) {
        float a = 0.f;
#pragma unroll
        for (int l = 0; l < NL; l++)
            a = fmaf(slat[tid * 12 + l], wp[l * NK + 128], a);
        sE128[tid] = __expf(a);
    }
    __syncthreads();

    double acc = 0.0;
    for (int c = w; c < CPB; c += 8) {
        int key = j * NC + (c0 + c);
        int cnt = __ldg(&g_cnt[key]);
        if (cnt == 0) continue;
        int st = __ldg(&g_start[key]);

        const float* sp = &slat[c * 12];
        const float4 la = *(const float4*)sp;
        const float4 lb = *(const float4*)(sp + 4);
        const float2 lc = *(const float2*)(sp + 8);
        float lv[NL] = {la.x, la.y, la.z, la.w, lb.x, lb.y, lb.z, lb.w, lc.x, lc.y};
        float a0 = 0.f, a1 = 0.f, a2 = 0.f, a3 = 0.f;
#pragma unroll
        for (int l = 0; l < NL; l++) {
            a0 = fmaf(lv[l], W0[l], a0);
            a1 = fmaf(lv[l], W1[l], a1);
            a2 = fmaf(lv[l], W2[l], a2);
            a3 = fmaf(lv[l], W3[l], a3);
        }
        float e0 = __expf(a0), e1 = __expf(a1);
        float e2 = __expf(a2), e3 = __expf(a3);
        float e128 = sE128[c];

        for (int t = 0; t < cnt; t++) {
            uint2 rec = __ldg(&g_rec[st + t]);          // broadcast (same addr)
            float x = __uint_as_float(rec.x);
            int gl = rec.y & 511;
            int q  = rec.y >> 9;

            uint2 br = *(const uint2*)&g_B[gl * 128 + k4];
            float2 b01 = __half22float2(*(const __half2*)&br.x);
            float2 b23 = __half22float2(*(const __half2*)&br.y);
            float u0 = e0 * b01.x;
            float u1 = e1 * b01.y;
            float u2 = e2 * b23.x;
            float u3 = e3 * b23.y;

            float s = u0 + u1 + u2 + u3;
            float u128 = 0.f;
            if (lane == 31) {
                u128 = e128 * __half2float(g_B128[gl]);
                s += 0.5f * u128;
            }
            if (lane == 0) s -= 0.5f * u0;

            float xs = fminf(fmaxf(x, 0.f), 0.999999f) * 128.f;
            int bi = (int)xs; if (bi > 127) bi = 127;
            float alpha = xs - (float)bi;

            int lb2 = bi >> 2, cb = bi & 3;
            int rk = bi + 1;
            int lr = (rk == 128) ? 31 : (rk >> 2);
            int cr = rk & 3;
            float selL = (cb == 0) ? u0 : (cb == 1) ? u1 : (cb == 2) ? u2 : u3;
            float selR = (cr == 0) ? u0 : (cr == 1) ? u1 : (cr == 2) ? u2 : u3;
            if (rk == 128) selR = u128;
            float L = __shfl_sync(FULL, selL, lb2);
            float R = __shfl_sync(FULL, selR, lr);

#pragma unroll
            for (int o = 16; o; o >>= 1) s += __shfl_xor_sync(FULL, s, o);

            if (lane == 0) {
                unsigned cq = (unsigned)q / (unsigned)NGT;
                float nl = __ldg(&g_logits[q]) - g_lse[cq];
                float val = __logf(fmaf(alpha, R - L, L)) - __logf(s) + C + nl;
                acc += (double)val;
            }
        }
    }

    __shared__ double shd[8];
    if (lane == 0) shd[w] = acc;
    __syncthreads();
    if (tid == 0) {
        double t = 0.0;
        for (int k = 0; k < 8; k++) t += shd[k];
        g_part[blockIdx.y * NGOI + blockIdx.x] = t;
    }
}

// ---------------- kernel: deterministic final reduce -------------------------
__global__ void k_final(float* __restrict__ out) {
    __shared__ double sh[256];
    double t = 0.0;
    for (int i = threadIdx.x; i < FUSED_BLOCKS; i += 256) t += g_part[i];
    sh[threadIdx.x] = t;
    __syncthreads();
    for (int s = 128; s; s >>= 1) {
        if (threadIdx.x < s) sh[threadIdx.x] += sh[threadIdx.x + s];
        __syncthreads();
    }
    if (threadIdx.x == 0) out[0] = (float)(-sh[0]);   // elbo = -sum(likelihood)
}

// ---------------- launch ------------------------------------------------------
extern "C" void kernel_launch(void* const* d_in, const int* in_sizes, int n_in,
                              void* d_out, int out_size) {
    const float* latent = (const float*)d_in[0];
    const float* coord  = (const float*)d_in[1];
    const int*   goi    = (const int*)  d_in[2];
    const int*   cxg    = (const int*)  d_in[3];   // cut_local_cellxgene_ix
    const int*   lcxg   = (const int*)  d_in[4];   // cut_localcellxgene_ix
    const int*   gloc   = (const int*)  d_in[5];   // cut_local_gene_ix
    const float* hw     = (const float*)d_in[6];   // height_slope_w
    const float* wo     = (const float*)d_in[7];   // overall_slope_w
    const float* ob     = (const float*)d_in[8];   // overall_baseline
    const float* sb     = (const float*)d_in[9];   // spline_baseline
    float* out = (float*)d_out;
    int ncuts = in_sizes[1];
    if (ncuts > MAXCUTS) ncuts = MAXCUTS;

    {
        dim3 grid((NGT + 255) / 256, (NC + 15) / 16);
        k_logits<<<grid, 256>>>(latent, wo, ob);
    }
    k_lse<<<NC, 512>>>();
    k_bexp<<<NGOI, 132>>>(sb, goi);

    k_zero<<<(NKEY + 255) / 256, 256>>>();
    k_hist<<<(ncuts + 255) / 256, 256>>>(cxg, ncuts);
    k_scanA<<<SNBLK, 256>>>();
    k_scanB<<<1, 512>>>();
    k_scanC<<<(NKEY + 255) / 256, 256>>>();
    k_scatter<<<(ncuts + 255) / 256, 256>>>(coord, cxg, lcxg, gloc, ncuts);

    {
        dim3 grid(NGOI, CSPLIT);
        k_fused<<<grid, 256>>>(latent, hw, goi);
    }
    k_final<<<1, 256>>>(out);
}

// round 7
// speedup vs baseline: 1.1991x; 1.1991x over previous
#include <cuda_runtime.h>
#include <cuda_fp16.h>
#include <cstdint>

// Problem constants (fixed by the dataset)
#define NC   1000      // cells
#define NGOI 500       // genes of interest
#define NGT  5000      // total genes
#define NL   10        // latent dim
#define NK   129       // knots (NBINS+1)
#define RSE  132       // E row stride in halves (264B, 8B-aligned)
#define NPAIR (NC*NGOI)

#define MAIN_BLOCKS 1184
#define MAIN_THREADS 256
#define CSPLIT 8              // cell splits in k_delta
#define CPB (NC / CSPLIT)     // 125 cells per block

// ---------------- device scratch (static: no allocation allowed) -------------
__device__ float  g_logits[NC * NGT];                 // 20 MB raw logits
__device__ float  g_lse[NC];
__device__ __half g_E[(size_t)NPAIR * RSE];           // 132 MB exp(delta), knots 0..128
__device__ __half g_B[NGOI * 128];                    // 128 KB exp(baseline) knots 0..127
__device__ __half g_B128[NGOI];                       // exp(baseline) knot 128
__device__ double g_part[MAIN_BLOCKS];

// ---------------- kernel: overall logits [NC x NGT] --------------------------
__global__ void k_logits(const float* __restrict__ latent,
                         const float* __restrict__ wo,
                         const float* __restrict__ ob) {
    __shared__ float lat[16 * NL];
    int g  = blockIdx.x * 256 + threadIdx.x;
    int c0 = blockIdx.y * 16;
    int t = threadIdx.x;
    if (t < 16 * NL) {
        int cc = c0 + t / NL;
        lat[t] = (cc < NC) ? latent[cc * NL + t % NL] : 0.f;
    }
    __syncthreads();
    if (g >= NGT) return;
    float w[NL];
#pragma unroll
    for (int l = 0; l < NL; l++) w[l] = wo[g * NL + l];
    float base = ob[g];
    int cmax = NC - c0; if (cmax > 16) cmax = 16;
    for (int c = 0; c < cmax; c++) {
        float a = base;
#pragma unroll
        for (int l = 0; l < NL; l++) a = fmaf(lat[c * NL + l], w[l], a);
        g_logits[(c0 + c) * NGT + g] = a;
    }
}

// ---------------- kernel: per-cell log-sum-exp (read-only) --------------------
__global__ void k_lse() {
    int c = blockIdx.x;
    const float4* row = (const float4*)&g_logits[c * NGT];
    float s = 0.f;
    for (int i = threadIdx.x; i < NGT / 4; i += 512) {
        float4 v = row[i];
        s += __expf(v.x) + __expf(v.y) + __expf(v.z) + __expf(v.w);
    }
    __shared__ float sh[16];
#pragma unroll
    for (int o = 16; o; o >>= 1) s += __shfl_xor_sync(0xffffffffu, s, o);
    if ((threadIdx.x & 31) == 0) sh[threadIdx.x >> 5] = s;
    __syncthreads();
    if (threadIdx.x < 16) {
        s = sh[threadIdx.x];
#pragma unroll
        for (int o = 8; o; o >>= 1) s += __shfl_xor_sync(0xffffu, s, o);
        if (threadIdx.x == 0) g_lse[c] = __logf(s);
    }
}

// ---------------- kernel: baseline exp table ----------------------------------
__global__ void k_bexp(const float* __restrict__ sb, const int* __restrict__ goi) {
    int j = blockIdx.x;
    int gene = goi[j];
    int t = threadIdx.x;
    if (t < NK) {
        __half v = __float2half_rn(__expf(sb[(size_t)gene * NK + t]));
        if (t < 128) g_B[j * 128 + t] = v;
        else         g_B128[j] = v;
    }
}

// ---------------- kernel: exp(delta) table, knots 0..128 ----------------------
// E[c*NGOI+j][k] = exp( sum_l latent[c][l] * hw[goi[j]][l][k] )
// One gene per blockIdx.x; W in registers; lane owns knots 4*lane..4*lane+3,
// lane (all lanes) also accumulates knot 128; lane 31 stores it.
__global__ void __launch_bounds__(256, 3) k_delta(const float* __restrict__ latent,
                                                  const float* __restrict__ hw,
                                                  const int*   __restrict__ goi) {
    __shared__ float slat[CPB * 12];        // latent slice, stride 12
    int j = blockIdx.x;
    int gene = goi[j];
    int c0 = blockIdx.y * CPB;
    int tid = threadIdx.x;
    int w = tid >> 5, lane = tid & 31;

    for (int i = tid; i < CPB * NL; i += 256) {
        int cc = i / NL, l = i - cc * NL;
        slat[cc * 12 + l] = latent[(c0 + cc) * NL + l];
    }

    int k4 = lane * 4;
    const float* wp = hw + (size_t)gene * NL * NK;
    float W0[NL], W1[NL], W2[NL], W3[NL], W4[NL];
#pragma unroll
    for (int l = 0; l < NL; l++) {
        const float* r = wp + l * NK;
        W0[l] = r[k4];     W1[l] = r[k4 + 1];
        W2[l] = r[k4 + 2]; W3[l] = r[k4 + 3];
        W4[l] = r[128];
    }
    __syncthreads();

    for (int c = w; c < CPB; c += 8) {
        const float* sp = &slat[c * 12];
        const float4 la = *(const float4*)sp;
        const float4 lb = *(const float4*)(sp + 4);
        const float2 lc = *(const float2*)(sp + 8);
        float lv[NL] = {la.x, la.y, la.z, la.w, lb.x, lb.y, lb.z, lb.w, lc.x, lc.y};
        float a0 = 0.f, a1 = 0.f, a2 = 0.f, a3 = 0.f, a4 = 0.f;
#pragma unroll
        for (int l = 0; l < NL; l++) {
            a0 = fmaf(lv[l], W0[l], a0);
            a1 = fmaf(lv[l], W1[l], a1);
            a2 = fmaf(lv[l], W2[l], a2);
            a3 = fmaf(lv[l], W3[l], a3);
            a4 = fmaf(lv[l], W4[l], a4);
        }
        __half2 h01 = __floats2half2_rn(__expf(a0), __expf(a1));
        __half2 h23 = __floats2half2_rn(__expf(a2), __expf(a3));
        uint2 st;
        st.x = *(const unsigned*)&h01;
        st.y = *(const unsigned*)&h23;
        size_t rb = ((size_t)(c0 + c) * NGOI + j) * RSE;
        *(uint2*)&g_E[rb + k4] = st;
        if (lane == 31) g_E[rb + 128] = __float2half_rn(__expf(a4));
    }
}

// ---------------- kernel: per-cut spline log-prob, warp per cut ---------------
__global__ void __launch_bounds__(MAIN_THREADS) k_main(
        const float* __restrict__ coord,
        const int*   __restrict__ cxg,    // pair index p
        const int*   __restrict__ lcxg,   // cell x total-gene index q
        const int*   __restrict__ gloc,   // local gene index gl
        int ncuts) {
    int w = threadIdx.x >> 5, lane = threadIdx.x & 31;
    int gw = blockIdx.x * (MAIN_THREADS >> 5) + w;
    int nw = gridDim.x * (MAIN_THREADS >> 5);
    int k4 = lane * 4;
    double acc = 0.0;
    const float C = 4.852030263919617f + 8.517193191416238f; // ln(128)+ln(5000)
    const unsigned FULL = 0xffffffffu;

    for (int i = gw; i < ncuts; i += nw) {
        int   p  = __ldg(&cxg[i]);
        int   gl = __ldg(&gloc[i]);
        float x  = __ldg(&coord[i]);

        size_t rb = (size_t)p * RSE;
        uint2 er = *(const uint2*)&g_E[rb + k4];
        uint2 br = *(const uint2*)&g_B[gl * 128 + k4];
        float2 e01 = __half22float2(*(const __half2*)&er.x);
        float2 e23 = __half22float2(*(const __half2*)&er.y);
        float2 b01 = __half22float2(*(const __half2*)&br.x);
        float2 b23 = __half22float2(*(const __half2*)&br.y);
        float u0 = e01.x * b01.x;
        float u1 = e01.y * b01.y;
        float u2 = e23.x * b23.x;
        float u3 = e23.y * b23.y;

        float s = u0 + u1 + u2 + u3;
        float u128 = 0.f;
        if (lane == 31) {
            u128 = __half2float(g_E[rb + 128]) * __half2float(g_B128[gl]);
            s += 0.5f * u128;                 // top endpoint (half weight)
        }
        if (lane == 0) s -= 0.5f * u0;        // halve bottom endpoint

        float xs = fminf(fmaxf(x, 0.f), 0.999999f) * 128.f;
        int bi = (int)xs; if (bi > 127) bi = 127;
        float alpha = xs - (float)bi;

        int lb = bi >> 2, cb = bi & 3;
        int rk = bi + 1;
        int lr = (rk == 128) ? 31 : (rk >> 2);
        int cr = rk & 3;
        float selL = (cb == 0) ? u0 : (cb == 1) ? u1 : (cb == 2) ? u2 : u3;
        float selR = (cr == 0) ? u0 : (cr == 1) ? u1 : (cr == 2) ? u2 : u3;
        if (rk == 128) selR = u128;
        float L = __shfl_sync(FULL, selL, lb);
        float R = __shfl_sync(FULL, selR, lr);

#pragma unroll
        for (int o = 16; o; o >>= 1) s += __shfl_xor_sync(FULL, s, o);

        if (lane == 0) {
            int q = __ldg(&lcxg[i]);
            unsigned cell = (unsigned)q / (unsigned)NGT;
            float nl = __ldg(&g_logits[q]) - g_lse[cell];
            float val = __logf(fmaf(alpha, R - L, L)) - __logf(s) + C + nl;
            acc += (double)val;
        }
    }

    __shared__ double sh[MAIN_THREADS / 32];
    if (lane == 0) sh[w] = acc;
    __syncthreads();
    if (threadIdx.x == 0) {
        double t = 0.0;
        for (int k = 0; k < MAIN_THREADS / 32; k++) t += sh[k];
        g_part[blockIdx.x] = t;
    }
}

// ---------------- kernel: deterministic final reduce -------------------------
__global__ void k_final(float* __restrict__ out) {
    __shared__ double sh[256];
    double t = 0.0;
    for (int i = threadIdx.x; i < MAIN_BLOCKS; i += 256) t += g_part[i];
    sh[threadIdx.x] = t;
    __syncthreads();
    for (int s = 128; s; s >>= 1) {
        if (threadIdx.x < s) sh[threadIdx.x] += sh[threadIdx.x + s];
        __syncthreads();
    }
    if (threadIdx.x == 0) out[0] = (float)(-sh[0]);   // elbo = -sum(likelihood)
}

// ---------------- launch ------------------------------------------------------
extern "C" void kernel_launch(void* const* d_in, const int* in_sizes, int n_in,
                              void* d_out, int out_size) {
    const float* latent = (const float*)d_in[0];
    const float* coord  = (const float*)d_in[1];
    const int*   goi    = (const int*)  d_in[2];
    const int*   cxg    = (const int*)  d_in[3];   // cut_local_cellxgene_ix
    const int*   lcxg   = (const int*)  d_in[4];   // cut_localcellxgene_ix
    const int*   gloc   = (const int*)  d_in[5];   // cut_local_gene_ix
    const float* hw     = (const float*)d_in[6];   // height_slope_w
    const float* wo     = (const float*)d_in[7];   // overall_slope_w
    const float* ob     = (const float*)d_in[8];   // overall_baseline
    const float* sb     = (const float*)d_in[9];   // spline_baseline
    float* out = (float*)d_out;
    int ncuts = in_sizes[1];

    {
        dim3 grid((NGT + 255) / 256, (NC + 15) / 16);
        k_logits<<<grid, 256>>>(latent, wo, ob);
    }
    k_lse<<<NC, 512>>>();
    k_bexp<<<NGOI, 132>>>(sb, goi);
    {
        dim3 grid(NGOI, CSPLIT);
        k_delta<<<grid, 256>>>(latent, hw, goi);
    }
    k_main<<<MAIN_BLOCKS, MAIN_THREADS>>>(coord, cxg, lcxg, gloc, ncuts);
    k_final<<<1, 256>>>(out);
}

// round 10
// speedup vs baseline: 1.8902x; 1.5764x over previous
#include <cuda_runtime.h>
#include <cuda_fp16.h>
#include <cstdint>

// Problem constants (fixed by the dataset)
#define NC   1000      // cells
#define NGOI 500       // genes of interest
#define NGT  5000      // total genes
#define NL   10        // latent dim
#define NK   129       // knots (NBINS+1)
#define RSE  136       // E row stride in halves (272B rows, 16B-aligned)
#define RSB  136       // B row stride in halves (272B rows, 16B-aligned)
#define NPAIR (NC*NGOI)

#define MAIN_BLOCKS 1184
#define MAIN_THREADS 256
#define CSPLIT 8
#define CPB (NC / CSPLIT)     // 125 cells per block

// ---------------- device scratch (static: no allocation allowed) -------------
__device__ float  g_logits[NC * NGT];                 // 20 MB raw logits
__device__ float  g_lse[NC];
__device__ __half g_E[(size_t)NPAIR * RSE];           // 136 MB exp(delta), knots 0..128
__device__ __half g_B[NGOI * RSB];                    // exp(baseline), knots 0..128
__device__ double g_part[MAIN_BLOCKS];

// ---------------- kernel: overall logits [NC x NGT] --------------------------
__global__ void k_logits(const float* __restrict__ latent,
                         const float* __restrict__ wo,
                         const float* __restrict__ ob) {
    __shared__ float lat[16 * NL];
    int g  = blockIdx.x * 256 + threadIdx.x;
    int c0 = blockIdx.y * 16;
    int t = threadIdx.x;
    if (t < 16 * NL) {
        int cc = c0 + t / NL;
        lat[t] = (cc < NC) ? latent[cc * NL + t % NL] : 0.f;
    }
    __syncthreads();
    if (g >= NGT) return;
    float w[NL];
#pragma unroll
    for (int l = 0; l < NL; l++) w[l] = wo[g * NL + l];
    float base = ob[g];
    int cmax = NC - c0; if (cmax > 16) cmax = 16;
    for (int c = 0; c < cmax; c++) {
        float a = base;
#pragma unroll
        for (int l = 0; l < NL; l++) a = fmaf(lat[c * NL + l], w[l], a);
        g_logits[(c0 + c) * NGT + g] = a;
    }
}

// ---------------- kernel: per-cell log-sum-exp --------------------------------
__global__ void k_lse() {
    int c = blockIdx.x;
    const float4* row = (const float4*)&g_logits[c * NGT];
    float s = 0.f;
    for (int i = threadIdx.x; i < NGT / 4; i += 512) {
        float4 v = row[i];
        s += __expf(v.x) + __expf(v.y) + __expf(v.z) + __expf(v.w);
    }
    __shared__ float sh[16];
#pragma unroll
    for (int o = 16; o; o >>= 1) s += __shfl_xor_sync(0xffffffffu, s, o);
    if ((threadIdx.x & 31) == 0) sh[threadIdx.x >> 5] = s;
    __syncthreads();
    if (threadIdx.x < 16) {
        s = sh[threadIdx.x];
#pragma unroll
        for (int o = 8; o; o >>= 1) s += __shfl_xor_sync(0xffffu, s, o);
        if (threadIdx.x == 0) g_lse[c] = __logf(s);
    }
}

// ---------------- kernel: baseline exp table ----------------------------------
__global__ void k_bexp(const float* __restrict__ sb, const int* __restrict__ goi) {
    int j = blockIdx.x;
    int gene = goi[j];
    int t = threadIdx.x;
    if (t < NK)
        g_B[j * RSB + t] = __float2half_rn(__expf(sb[(size_t)gene * NK + t]));
}

// ---------------- kernel: exp(delta) fp16 table, knots 0..128 -----------------
// E[c*NGOI+j][k] = exp( sum_l latent[c][l] * hw[goi[j]][l][k] )
__global__ void __launch_bounds__(256, 3) k_delta(const float* __restrict__ latent,
                                                  const float* __restrict__ hw,
                                                  const int*   __restrict__ goi) {
    __shared__ float slat[CPB * 12];
    int j = blockIdx.x;
    int gene = goi[j];
    int c0 = blockIdx.y * CPB;
    int tid = threadIdx.x;
    int w = tid >> 5, lane = tid & 31;

    for (int i = tid; i < CPB * NL; i += 256) {
        int cc = i / NL, l = i - cc * NL;
        slat[cc * 12 + l] = latent[(c0 + cc) * NL + l];
    }

    int k4 = lane * 4;
    const float* wp = hw + (size_t)gene * NL * NK;
    float W0[NL], W1[NL], W2[NL], W3[NL], W4[NL];
#pragma unroll
    for (int l = 0; l < NL; l++) {
        const float* r = wp + l * NK;
        W0[l] = r[k4];     W1[l] = r[k4 + 1];
        W2[l] = r[k4 + 2]; W3[l] = r[k4 + 3];
        W4[l] = r[128];
    }
    __syncthreads();

    for (int c = w; c < CPB; c += 8) {
        const float* sp = &slat[c * 12];
        const float4 la = *(const float4*)sp;
        const float4 lb = *(const float4*)(sp + 4);
        const float2 lc = *(const float2*)(sp + 8);
        float lv[NL] = {la.x, la.y, la.z, la.w, lb.x, lb.y, lb.z, lb.w, lc.x, lc.y};
        float a0 = 0.f, a1 = 0.f, a2 = 0.f, a3 = 0.f, a4 = 0.f;
#pragma unroll
        for (int l = 0; l < NL; l++) {
            a0 = fmaf(lv[l], W0[l], a0);
            a1 = fmaf(lv[l], W1[l], a1);
            a2 = fmaf(lv[l], W2[l], a2);
            a3 = fmaf(lv[l], W3[l], a3);
            a4 = fmaf(lv[l], W4[l], a4);
        }
        __half2 h01 = __floats2half2_rn(__expf(a0), __expf(a1));
        __half2 h23 = __floats2half2_rn(__expf(a2), __expf(a3));
        uint2 st;
        st.x = *(const unsigned*)&h01;
        st.y = *(const unsigned*)&h23;
        size_t rb = (size_t)((c0 + c) * NGOI + j) * RSE;
        *(uint2*)&g_E[rb + k4] = st;
        if (lane == 31) g_E[rb + 128] = __float2half_rn(__expf(a4));
    }
}

// ---------------- kernel: per-cut spline log-prob, 8-lane groups --------------
// Warp handles 4 cuts; each 8-lane group reduces one cut's 129-knot trapezoid
// norm (lane owns 16 knots); the sub==0 lane does L/R interp + final logs.
__global__ void __launch_bounds__(MAIN_THREADS) k_main(
        const float* __restrict__ coord,
        const int*   __restrict__ cxg,    // pair index p
        const int*   __restrict__ lcxg,   // cell x total-gene index q
        const int*   __restrict__ gloc,   // local gene index gl
        int ncuts) {
    int lane = threadIdx.x & 31, w = threadIdx.x >> 5;
    int grp = lane >> 3, sub = lane & 7;
    int warpid = blockIdx.x * (MAIN_THREADS >> 5) + w;
    int nwarp = gridDim.x * (MAIN_THREADS >> 5);
    double acc = 0.0;
    const float C = 4.852030263919617f + 8.517193191416238f; // ln(128)+ln(5000)
    const unsigned FULL = 0xffffffffu;

    for (int i4 = warpid * 4; i4 < ncuts; i4 += nwarp * 4) {
        int cut = i4 + grp;
        int cc = (cut < ncuts) ? cut : (ncuts - 1);
        int p  = __ldg(&cxg[cc]);
        int gl = __ldg(&gloc[cc]);

        size_t rb = (size_t)p * RSE;
        const __half* erow = &g_E[rb + sub * 16];
        const __half* brow = &g_B[gl * RSB + sub * 16];
        const uint4 ev0 = *(const uint4*)erow;
        const uint4 ev1 = *(const uint4*)(erow + 8);
        const uint4 bv0 = *(const uint4*)brow;
        const uint4 bv1 = *(const uint4*)(brow + 8);

        __half2 t0 = __hmul2(*(const __half2*)&ev0.x, *(const __half2*)&bv0.x);
        __half2 t1 = __hmul2(*(const __half2*)&ev0.y, *(const __half2*)&bv0.y);
        __half2 t2 = __hmul2(*(const __half2*)&ev0.z, *(const __half2*)&bv0.z);
        __half2 t3 = __hmul2(*(const __half2*)&ev0.w, *(const __half2*)&bv0.w);
        __half2 t4 = __hmul2(*(const __half2*)&ev1.x, *(const __half2*)&bv1.x);
        __half2 t5 = __hmul2(*(const __half2*)&ev1.y, *(const __half2*)&bv1.y);
        __half2 t6 = __hmul2(*(const __half2*)&ev1.z, *(const __half2*)&bv1.z);
        __half2 t7 = __hmul2(*(const __half2*)&ev1.w, *(const __half2*)&bv1.w);

        __half2 t = __hadd2(__hadd2(__hadd2(t0, t1), __hadd2(t2, t3)),
                            __hadd2(__hadd2(t4, t5), __hadd2(t6, t7)));
        float2 tf = __half22float2(t);
        float s = tf.x + tf.y;
        if (sub == 0) s -= 0.5f * __low2float(t0);            // halve bottom endpoint
        if (sub == 7) {
            float u128 = __half2float(g_E[rb + 128]) * __half2float(g_B[gl * RSB + 128]);
            s += 0.5f * u128;                                  // top endpoint (half)
        }
        s += __shfl_xor_sync(FULL, s, 1);
        s += __shfl_xor_sync(FULL, s, 2);
        s += __shfl_xor_sync(FULL, s, 4);

        // ---- interp + final math on sub==0 lanes (L1-hit scalar loads) -------
        if (sub == 0 && cut < ncuts) {
            float x = __ldg(&coord[cc]);
            int   q = __ldg(&lcxg[cc]);

            float xs = fminf(fmaxf(x, 0.f), 0.999999f) * 128.f;
            int bi = (int)xs; if (bi > 127) bi = 127;
            float alpha = xs - (float)bi;

            float L = __half2float(g_E[rb + bi])     * __half2float(g_B[gl * RSB + bi]);
            float R = __half2float(g_E[rb + bi + 1]) * __half2float(g_B[gl * RSB + bi + 1]);
            float nl = __ldg(&g_logits[q]) - g_lse[(unsigned)q / (unsigned)NGT];
            float val = __logf(fmaf(alpha, R - L, L)) - __logf(s) + C + nl;
            acc += (double)val;
        }
    }

    __shared__ double sh[MAIN_THREADS];
    sh[threadIdx.x] = acc;
    __syncthreads();
    for (int o = MAIN_THREADS / 2; o; o >>= 1) {
        if (threadIdx.x < o) sh[threadIdx.x] += sh[threadIdx.x + o];
        __syncthreads();
    }
    if (threadIdx.x == 0) g_part[blockIdx.x] = sh[0];
}

// ---------------- kernel: deterministic final reduce -------------------------
__global__ void k_final(float* __restrict__ out) {
    __shared__ double sh[256];
    double t = 0.0;
    for (int i = threadIdx.x; i < MAIN_BLOCKS; i += 256) t += g_part[i];
    sh[threadIdx.x] = t;
    __syncthreads();
    for (int s = 128; s; s >>= 1) {
        if (threadIdx.x < s) sh[threadIdx.x] += sh[threadIdx.x + s];
        __syncthreads();
    }
    if (threadIdx.x == 0) out[0] = (float)(-sh[0]);   // elbo = -sum(likelihood)
}

// ---------------- launch ------------------------------------------------------
extern "C" void kernel_launch(void* const* d_in, const int* in_sizes, int n_in,
                              void* d_out, int out_size) {
    const float* latent = (const float*)d_in[0];
    const float* coord  = (const float*)d_in[1];
    const int*   goi    = (const int*)  d_in[2];
    const int*   cxg    = (const int*)  d_in[3];   // cut_local_cellxgene_ix
    const int*   lcxg   = (const int*)  d_in[4];   // cut_localcellxgene_ix
    const int*   gloc   = (const int*)  d_in[5];   // cut_local_gene_ix
    const float* hw     = (const float*)d_in[6];   // height_slope_w
    const float* wo     = (const float*)d_in[7];   // overall_slope_w
    const float* ob     = (const float*)d_in[8];   // overall_baseline
    const float* sb     = (const float*)d_in[9];   // spline_baseline
    float* out = (float*)d_out;
    int ncuts = in_sizes[1];

    {
        dim3 grid((NGT + 255) / 256, (NC + 15) / 16);
        k_logits<<<grid, 256>>>(latent, wo, ob);
    }
    k_lse<<<NC, 512>>>();
    k_bexp<<<NGOI, 132>>>(sb, goi);
    {
        dim3 grid(NGOI, CSPLIT);
        k_delta<<<grid, 256>>>(latent, hw, goi);
    }
    k_main<<<MAIN_BLOCKS, MAIN_THREADS>>>(coord, cxg, lcxg, gloc, ncuts);
    k_final<<<1, 256>>>(out);
}